// round 14
// baseline (speedup 1.0000x reference)
#include <cuda_runtime.h>
#include <cuda_fp16.h>
#include <math.h>
#include <cstdint>

// Problem constants
#define B_   8
#define C_   256
#define H_   64
#define W_   64
#define O_   256
#define KK_  9
#define HW_  (H_*W_)          // 4096
#define KDIM (C_*KK_)         // 2304

#define CK     64             // K per chunk
#define NCH    36             // 9 kk * 4 c-chunks of 64

// ---------------------------------------------------------------------------
// Scratch (device globals; allocation-free)
// ---------------------------------------------------------------------------
__device__ float g_offset[B_ * 18 * HW_];
__device__ __align__(16) uint2 g_xq[B_ * C_ * HW_];       // 2x2 fp16 quads (67MB)
__device__ __align__(16) __half g_Bhi[NCH * CK * O_];     // w_dcn fp16 [36][64k][256n]
__device__ __align__(16) __half g_WoffHi[NCH * CK * 32];  // w_off hi [36][64k][32n]
__device__ __align__(16) __half g_WoffLo[NCH * CK * 32];

// ---------------------------------------------------------------------------
// helpers
// ---------------------------------------------------------------------------
__device__ __forceinline__ uint32_t smem_u32(const void* p) {
    uint32_t a;
    asm("{ .reg .u64 t; cvta.to.shared.u64 t, %1; cvt.u32.u64 %0, t; }" : "=r"(a) : "l"(p));
    return a;
}

#define LDSM_X4(r, addr) \
    asm volatile("ldmatrix.sync.aligned.m8n8.x4.shared.b16 {%0,%1,%2,%3}, [%4];" \
        : "=r"((r)[0]), "=r"((r)[1]), "=r"((r)[2]), "=r"((r)[3]) : "r"(addr))

#define LDSM_X4T(r, addr) \
    asm volatile("ldmatrix.sync.aligned.m8n8.x4.trans.shared.b16 {%0,%1,%2,%3}, [%4];" \
        : "=r"((r)[0]), "=r"((r)[1]), "=r"((r)[2]), "=r"((r)[3]) : "r"(addr))

#define MMA16816(d, a, b0, b1) \
    asm volatile("mma.sync.aligned.m16n8k16.row.col.f32.f16.f16.f32 " \
        "{%0,%1,%2,%3}, {%4,%5,%6,%7}, {%8,%9}, {%0,%1,%2,%3};" \
        : "+f"((d)[0]), "+f"((d)[1]), "+f"((d)[2]), "+f"((d)[3]) \
        : "r"((a)[0]), "r"((a)[1]), "r"((a)[2]), "r"((a)[3]), "r"(b0), "r"(b1))

#define CP_ASYNC16(dst, src) \
    asm volatile("cp.async.cg.shared.global [%0], [%1], 16;" :: "r"(dst), "l"(src))
#define CP_COMMIT() asm volatile("cp.async.commit_group;" ::: "memory")
#define CP_WAIT0()  asm volatile("cp.async.wait_group 0;" ::: "memory")

// ---------------------------------------------------------------------------
// Kernel 0: build 2x2 fp16 quad array.
// ---------------------------------------------------------------------------
__global__ void prep_xquad_kernel(const float* __restrict__ x) {
    int idx = blockIdx.x * 256 + threadIdx.x;       // B*C*HW = 8388608
    if (idx >= B_ * C_ * HW_) return;
    int w = idx & (W_ - 1);
    int y = (idx >> 6) & (H_ - 1);
    float v00 = x[idx];
    float v01 = (w < W_ - 1) ? x[idx + 1] : 0.f;
    float v10 = (y < H_ - 1) ? x[idx + W_] : 0.f;
    float v11 = (w < W_ - 1 && y < H_ - 1) ? x[idx + W_ + 1] : 0.f;
    __half2 r0 = __floats2half2_rn(v00, v01);
    __half2 r1 = __floats2half2_rn(v10, v11);
    uint2 q;
    q.x = *(uint32_t*)&r0;
    q.y = *(uint32_t*)&r1;
    g_xq[idx] = q;
}

// ---------------------------------------------------------------------------
// Kernel 1a: w_dcn -> g_Bhi (fp16)
// ---------------------------------------------------------------------------
__global__ void prep_b_kernel(const float* __restrict__ w_dcn) {
    int idx = blockIdx.x * 256 + threadIdx.x;
    if (idx >= O_ * C_) return;
    int o = idx >> 8, c = idx & 255;
    int cb = c >> 6, k = c & 63;
    const float* src = w_dcn + ((size_t)o * C_ + c) * KK_;
#pragma unroll
    for (int kk = 0; kk < KK_; kk++) {
        g_Bhi[(size_t)(kk * 4 + cb) * (CK * O_) + k * O_ + o] = __float2half_rn(src[kk]);
    }
}

// ---------------------------------------------------------------------------
// Kernel 1b: w_off -> g_WoffHi/Lo
// ---------------------------------------------------------------------------
__global__ void prep_woff_kernel(const float* __restrict__ w_off) {
    int idx = blockIdx.x * 256 + threadIdx.x;
    if (idx >= NCH * CK * 32) return;
    int q  = idx >> 11;
    int r  = idx & 2047;
    int k  = r >> 5;
    int oc = r & 31;
    int kk = q >> 2, cb = q & 3;
    int c  = cb * 64 + k;
    float v = (oc < 18) ? w_off[((size_t)oc * C_ + c) * KK_ + kk] : 0.f;
    __half hi = __float2half_rn(v);
    __half lo = __float2half_rn(v - __half2float(hi));
    g_WoffHi[idx] = hi;
    g_WoffLo[idx] = lo;
}

// ---------------------------------------------------------------------------
// Kernel 2: offset conv via mma.sync, 2-term (AhBh + AhBl), A direct fp16.
// M=256 per CTA (4 h rows), 512 threads / 16 warps (8m x 2n), warp 32x16.
// smem: AsHi[256][72] @0 (36864), BsHi[64][40] @36864 (5120), BsLo @41984.
// ---------------------------------------------------------------------------
#define OA_STR 72
#define OB_STR 40
#define OSM_BHI 36864
#define OSM_BLO 41984

__global__ __launch_bounds__(512, 1) void offset_mma_kernel(
    const float* __restrict__ x, const float* __restrict__ b_off) {
    __shared__ __align__(16) char sm[47104];
    __half (*AsHi)[OA_STR] = (__half(*)[OA_STR])(sm);
    __half (*BsHi)[OB_STR] = (__half(*)[OB_STR])(sm + OSM_BHI);
    __half (*BsLo)[OB_STR] = (__half(*)[OB_STR])(sm + OSM_BLO);

    int tid = threadIdx.x, lane = tid & 31, wid = tid >> 5;
    int blk = blockIdx.x;                 // 0..127
    int b = blk >> 4, h0 = (blk & 15) * 4;
    int wm = wid >> 1, wn = wid & 1;
    int m0 = wm * 32, n0 = wn * 16;

    int m  = tid & 255;                   // M row: h_local = m>>6, w = m&63
    int cg = tid >> 8;                    // 0..1: 32 channels each
    int hh = h0 + (m >> 6);
    int wp = m & 63;
    const float* xb = x + (size_t)b * C_ * HW_;

    uint32_t aHi = smem_u32(sm) +
        (uint32_t)(((m0 + (lane & 15)) * OA_STR + ((lane >> 4) * 8)) * 2);
    uint32_t bHi = smem_u32(sm) + OSM_BHI +
        (uint32_t)(((((lane & 7) + 8 * ((lane >> 3) & 1)) * OB_STR) + n0 + 8 * (lane >> 4)) * 2);

    float d[2][2][4];
#pragma unroll
    for (int i = 0; i < 2; i++)
#pragma unroll
        for (int j = 0; j < 2; j++)
#pragma unroll
            for (int k = 0; k < 4; k++) d[i][j][k] = 0.f;

#pragma unroll 1
    for (int kk = 0; kk < KK_; kk++) {
        int ky = kk / 3, kx = kk % 3;
        int hy = hh - 1 + ky;
        int wx = wp - 1 + kx;
        bool vr = (hy >= 0 && hy < H_ && wx >= 0 && wx < W_);
        const float* xrow = xb + hy * W_ + wx;    // + c*HW_

#pragma unroll 1
        for (int cb = 0; cb < 4; cb++) {
            int q  = kk * 4 + cb;
            int c0 = cb * 64;

            // B fill (first 256 threads)
            if (tid < 256) {
                const float4* sH = (const float4*)(g_WoffHi + (size_t)q * (CK * 32));
                const float4* sL = (const float4*)(g_WoffLo + (size_t)q * (CK * 32));
                int row = tid >> 2, c4 = tid & 3;
                *(float4*)(&BsHi[row][c4 * 8]) = sH[tid];
                *(float4*)(&BsLo[row][c4 * 8]) = sL[tid];
            }

            // A fill: 32 channels/thread, fp16 direct (coalesced NCHW)
#pragma unroll
            for (int p = 0; p < 4; p++) {
                int cl = cg * 32 + 8 * p;
                __half2 hi[4];
#pragma unroll
                for (int u = 0; u < 4; u++) {
                    int c = c0 + cl + 2 * u;
                    float v0 = vr ? __ldg(xrow + (size_t)c * HW_) : 0.f;
                    float v1 = vr ? __ldg(xrow + (size_t)(c + 1) * HW_) : 0.f;
                    hi[u] = __floats2half2_rn(v0, v1);
                }
                *(float4*)(&AsHi[m][cl]) = *(float4*)hi;
            }
            __syncthreads();

#pragma unroll
            for (int ks = 0; ks < 4; ks++) {
                uint32_t a[2][4], bh[4], bl[4];
                uint32_t aOff = (uint32_t)(ks * 32);
                uint32_t bOff = (uint32_t)(ks * 16 * OB_STR * 2);
                LDSM_X4T(bh, bHi + bOff);
                LDSM_X4T(bl, bHi + (OSM_BLO - OSM_BHI) + bOff);
#pragma unroll
                for (int mt = 0; mt < 2; mt++)
                    LDSM_X4(a[mt], aHi + aOff + mt * (16 * OA_STR * 2));
#pragma unroll
                for (int mt = 0; mt < 2; mt++)
#pragma unroll
                    for (int nt = 0; nt < 2; nt++) {
                        MMA16816(d[mt][nt], a[mt], bh[nt * 2], bh[nt * 2 + 1]);
                        MMA16816(d[mt][nt], a[mt], bl[nt * 2], bl[nt * 2 + 1]);
                    }
            }
            __syncthreads();
        }
    }

#pragma unroll
    for (int mt = 0; mt < 2; mt++)
#pragma unroll
        for (int nt = 0; nt < 2; nt++)
#pragma unroll
            for (int r = 0; r < 4; r++) {
                int mm = m0 + mt * 16 + (lane >> 2) + ((r >= 2) ? 8 : 0);
                int oc = n0 + nt * 8 + (lane & 3) * 2 + (r & 1);
                if (oc < 18) {
                    g_offset[((b * 18 + oc) * H_ + h0 + (mm >> 6)) * W_ + (mm & 63)]
                        = d[mt][nt][r] + __ldg(b_off + oc);
                }
            }
}

// ---------------------------------------------------------------------------
// Kernel 3: fused bilinear sample + mma.sync single-term fp16 GEMM
// CTA = one (b,h): M=64, N=256. 256 threads / 8 warps (2m x 4n), warp 32x64.
// CHUNK-PAIR pipeline: fill A(q0),A(q1) (32 gathers in flight) -> sync ->
// MMA both -> sync -> prefetch next B pair (hidden behind next A fill).
// smem (dynamic 86016B): AsHi[2] @0 (2x9216), Bs[2] @18432 (2x33792),
// epilogue float buf[128][66] (33792) reuses @0.
// ---------------------------------------------------------------------------
#define A_STR 72
#define B_STR 264
#define A_BUF 9216
#define SM_B   18432
#define B_BUF  33792
#define SM_TOT 86016

__device__ __forceinline__ void prefetch_b(uint32_t bs_base, int q, int tid) {
    const float4* src = (const float4*)(g_Bhi + (size_t)q * (CK * O_));
#pragma unroll
    for (int i = 0; i < 8; i++) {
        int e = tid + 256 * i;
        int row = e >> 5, c4 = e & 31;
        uint32_t dst = bs_base + (uint32_t)(row * B_STR + c4 * 8) * 2;
        CP_ASYNC16(dst, src + e);
    }
}

__global__ __launch_bounds__(256, 2) void dcn_mma_kernel(float* __restrict__ out) {
    extern __shared__ __align__(16) char sm[];
    uint32_t smb = smem_u32(sm);

    int tid = threadIdx.x, lane = tid & 31, wid = tid >> 5;
    int wm = wid >> 2, wn = wid & 3;
    int m0 = wm * 32, n0 = wn * 64;

    int blk = blockIdx.x;
    int b = blk >> 6, h = blk & 63;
    const uint2* xq_b = g_xq + (size_t)b * C_ * HW_;

    int m  = tid & 63;          // w position
    int cg = tid >> 6;          // 0..3: 16 channels each

    uint32_t aHi = smb +
        (uint32_t)(((m0 + (lane & 15)) * A_STR + ((lane >> 4) * 8)) * 2);
    uint32_t bBase = smb + SM_B +
        (uint32_t)(((((lane & 7) + 8 * ((lane >> 3) & 1)) * B_STR) + n0 + 8 * (lane >> 4)) * 2);

    float d[2][8][4];
#pragma unroll
    for (int i = 0; i < 2; i++)
#pragma unroll
        for (int j = 0; j < 8; j++)
#pragma unroll
            for (int k = 0; k < 4; k++) d[i][j][k] = 0.f;

    // prologue: prefetch B chunks 0 and 1 into both buffers
    prefetch_b(smb + SM_B, 0, tid);
    prefetch_b(smb + SM_B + B_BUF, 1, tid);
    CP_COMMIT();

    int q = 0;

#pragma unroll 1
    for (int kk = 0; kk < KK_; kk++) {
        int ky = kk / 3, kx = kk % 3;
        float offy = g_offset[((b * 18 + kk * 2 + 0) * H_ + h) * W_ + m];
        float offx = g_offset[((b * 18 + kk * 2 + 1) * H_ + h) * W_ + m];
        float sy = offy + (float)(h - 1 + ky);
        float sx = offx + (float)(m - 1 + kx);
        float fy0 = floorf(sy), fx0 = floorf(sx);
        float fy = sy - fy0, fx = sx - fx0;
        int iy = (int)fy0, ix = (int)fx0;

        // x-pair weights (validity folded in; pad slots hold 0)
        float wa, wb; int px;
        if (ix >= 0 && ix < W_ - 1)      { wa = 1.f - fx; wb = fx;  px = ix; }
        else if (ix == -1)               { wa = fx;       wb = 0.f; px = 0; }
        else if (ix == W_ - 1)           { wa = 1.f - fx; wb = 0.f; px = W_ - 1; }
        else                             { wa = 0.f;      wb = 0.f; px = 0; }

        // y handling: quad at row py covers rows py, py+1
        float w00, w01, w10, w11; int py;
        if (iy >= 0 && iy < H_) {
            float wy0 = 1.f - fy;
            float wy1 = (iy + 1 < H_) ? fy : 0.f;
            py = iy;
            w00 = wa * wy0; w01 = wb * wy0; w10 = wa * wy1; w11 = wb * wy1;
        } else if (iy == -1) {
            py = 0;
            w00 = wa * fy; w01 = wb * fy; w10 = 0.f; w11 = 0.f;
        } else {
            py = 0; w00 = w01 = w10 = w11 = 0.f;
        }

        const uint2* qbase = xq_b + py * W_ + px;   // + c*HW_

        // two chunk-pairs per kk: (cb 0,1) and (cb 2,3)
#pragma unroll 1
        for (int cbp = 0; cbp < 4; cbp += 2) {
            // ---- fill A for BOTH chunks of the pair (32 gathers in flight) ----
#pragma unroll
            for (int half = 0; half < 2; half++) {
                int c0 = (cbp + half) * 64;
                char* aDst = sm + half * A_BUF + (m * A_STR) * 2;
#pragma unroll
                for (int p = 0; p < 2; p++) {
                    int cl = cg * 16 + 8 * p;
                    __half2 hi[4];
#pragma unroll
                    for (int u = 0; u < 4; u++) {
                        int c = c0 + cl + 2 * u;
                        uint2 qa = __ldg(qbase + (size_t)c * HW_);
                        uint2 qb = __ldg(qbase + (size_t)(c + 1) * HW_);
                        float2 a01 = __half22float2(*(__half2*)&qa.x);
                        float2 a23 = __half22float2(*(__half2*)&qa.y);
                        float2 b01 = __half22float2(*(__half2*)&qb.x);
                        float2 b23 = __half22float2(*(__half2*)&qb.y);
                        float v0 = w00 * a01.x + w01 * a01.y + w10 * a23.x + w11 * a23.y;
                        float v1 = w00 * b01.x + w01 * b01.y + w10 * b23.x + w11 * b23.y;
                        hi[u] = __floats2half2_rn(v0, v1);
                    }
                    *(float4*)(aDst + cl * 2) = *(float4*)hi;
                }
            }

            // B pair arrived + A stores visible
            CP_WAIT0();
            __syncthreads();

            // ---- MMA on both chunks ----
#pragma unroll
            for (int half = 0; half < 2; half++) {
                uint32_t aAddr = aHi + half * A_BUF;
                uint32_t bAddr = bBase + half * B_BUF;
#pragma unroll
                for (int ks = 0; ks < 4; ks++) {
                    uint32_t a[2][4], bf[4][4];
                    uint32_t aOff = (uint32_t)(ks * 32);
                    uint32_t bOff = (uint32_t)(ks * 16 * B_STR * 2);
#pragma unroll
                    for (int nq = 0; nq < 4; nq++) LDSM_X4T(bf[nq], bAddr + bOff + nq * 32);
#pragma unroll
                    for (int mt = 0; mt < 2; mt++) LDSM_X4(a[mt], aAddr + aOff + mt * (16 * A_STR * 2));
#pragma unroll
                    for (int mt = 0; mt < 2; mt++)
#pragma unroll
                        for (int nt = 0; nt < 8; nt++)
                            MMA16816(d[mt][nt], a[mt], bf[nt >> 1][(nt & 1) * 2], bf[nt >> 1][(nt & 1) * 2 + 1]);
                }
            }

            // all warps done reading B buffers before overwrite
            __syncthreads();

            if (q < NCH - 2) {
                prefetch_b(smb + SM_B, q + 2, tid);
                prefetch_b(smb + SM_B + B_BUF, q + 3, tid);
                CP_COMMIT();
            }
            q += 2;
        }
    }

    // (last sync of the loop already executed)

    // epilogue: smem transpose -> coalesced stores
    float (*bufp)[66] = (float(*)[66])(sm);
#pragma unroll 1
    for (int pass = 0; pass < 2; pass++) {
        if ((wn >> 1) == pass) {
            int nb = n0 - pass * 128;
#pragma unroll
            for (int mt = 0; mt < 2; mt++)
#pragma unroll
                for (int nt = 0; nt < 8; nt++) {
                    int rrow = m0 + mt * 16 + (lane >> 2);
                    int ccol = nb + nt * 8 + 2 * (lane & 3);
                    bufp[ccol][rrow]         = d[mt][nt][0];
                    bufp[ccol + 1][rrow]     = d[mt][nt][1];
                    bufp[ccol][rrow + 8]     = d[mt][nt][2];
                    bufp[ccol + 1][rrow + 8] = d[mt][nt][3];
                }
        }
        __syncthreads();
        float* obase = out + ((size_t)b * O_ + pass * 128) * HW_ + h * 64;
#pragma unroll
        for (int i = 0; i < 16; i++) {
            int e = tid + 256 * i;
            int nl = e >> 5, c2 = e & 31;
            float2 v = *(float2*)(&bufp[nl][c2 * 2]);
            *(float2*)(obase + (size_t)nl * HW_ + c2 * 2) = v;
        }
        __syncthreads();
    }
}

// ---------------------------------------------------------------------------
// Launch
// ---------------------------------------------------------------------------
extern "C" void kernel_launch(void* const* d_in, const int* in_sizes, int n_in,
                              void* d_out, int out_size) {
    const float* x     = (const float*)d_in[0];
    const float* w_off = (const float*)d_in[1];
    const float* b_off = (const float*)d_in[2];
    const float* w_dcn = (const float*)d_in[3];
    float* out = (float*)d_out;

    cudaFuncSetAttribute(dcn_mma_kernel,
                         cudaFuncAttributeMaxDynamicSharedMemorySize, SM_TOT);

    prep_xquad_kernel<<<(B_ * C_ * HW_ + 255) / 256, 256>>>(x);
    prep_b_kernel<<<(O_ * C_ + 255) / 256, 256>>>(w_dcn);
    prep_woff_kernel<<<(NCH * CK * 32 + 255) / 256, 256>>>(w_off);
    offset_mma_kernel<<<B_ * H_ / 4, 512>>>(x, b_off);
    dcn_mma_kernel<<<B_ * H_, 256, SM_TOT>>>(out);
}

// round 15
// speedup vs baseline: 1.1494x; 1.1494x over previous
#include <cuda_runtime.h>
#include <cuda_fp16.h>
#include <math.h>
#include <cstdint>

// Problem constants
#define B_   8
#define C_   256
#define H_   64
#define W_   64
#define O_   256
#define KK_  9
#define HW_  (H_*W_)          // 4096
#define KDIM (C_*KK_)         // 2304

#define CK     64             // K per chunk
#define NCH    36             // 9 kk * 4 c-chunks of 64

// ---------------------------------------------------------------------------
// Scratch (device globals; allocation-free)
// ---------------------------------------------------------------------------
__device__ float g_offset[B_ * 18 * HW_];
__device__ __align__(16) __half2 g_xph[B_ * C_ * HW_];    // (x[w], x[w+1]) fp16 pairs
__device__ __align__(16) __half g_Bhi[NCH * CK * O_];     // w_dcn fp16 [36][64k][256n]
__device__ __align__(16) __half g_WoffHi[NCH * CK * 32];  // w_off hi [36][64k][32n]
__device__ __align__(16) __half g_WoffLo[NCH * CK * 32];

// ---------------------------------------------------------------------------
// helpers
// ---------------------------------------------------------------------------
__device__ __forceinline__ uint32_t smem_u32(const void* p) {
    uint32_t a;
    asm("{ .reg .u64 t; cvta.to.shared.u64 t, %1; cvt.u32.u64 %0, t; }" : "=r"(a) : "l"(p));
    return a;
}

#define LDSM_X4(r, addr) \
    asm volatile("ldmatrix.sync.aligned.m8n8.x4.shared.b16 {%0,%1,%2,%3}, [%4];" \
        : "=r"((r)[0]), "=r"((r)[1]), "=r"((r)[2]), "=r"((r)[3]) : "r"(addr))

#define LDSM_X4T(r, addr) \
    asm volatile("ldmatrix.sync.aligned.m8n8.x4.trans.shared.b16 {%0,%1,%2,%3}, [%4];" \
        : "=r"((r)[0]), "=r"((r)[1]), "=r"((r)[2]), "=r"((r)[3]) : "r"(addr))

#define MMA16816(d, a, b0, b1) \
    asm volatile("mma.sync.aligned.m16n8k16.row.col.f32.f16.f16.f32 " \
        "{%0,%1,%2,%3}, {%4,%5,%6,%7}, {%8,%9}, {%0,%1,%2,%3};" \
        : "+f"((d)[0]), "+f"((d)[1]), "+f"((d)[2]), "+f"((d)[3]) \
        : "r"((a)[0]), "r"((a)[1]), "r"((a)[2]), "r"((a)[3]), "r"(b0), "r"(b1))

#define CP_ASYNC16(dst, src) \
    asm volatile("cp.async.cg.shared.global [%0], [%1], 16;" :: "r"(dst), "l"(src))
#define CP_COMMIT() asm volatile("cp.async.commit_group;" ::: "memory")
#define CP_WAIT0()  asm volatile("cp.async.wait_group 0;" ::: "memory")

// ---------------------------------------------------------------------------
// Kernel 0: build fp16 x-pair array: g_xph[idx] = (x[idx], x[idx+1] | 0)
// ---------------------------------------------------------------------------
__global__ void prep_xpair_kernel(const float* __restrict__ x) {
    int idx = blockIdx.x * 256 + threadIdx.x;       // B*C*HW = 8388608
    if (idx >= B_ * C_ * HW_) return;
    float v0 = x[idx];
    int w = idx & (W_ - 1);
    float v1 = (w < W_ - 1) ? x[idx + 1] : 0.f;
    g_xph[idx] = __floats2half2_rn(v0, v1);
}

// ---------------------------------------------------------------------------
// Kernel 1a: w_dcn -> g_Bhi (fp16)
// ---------------------------------------------------------------------------
__global__ void prep_b_kernel(const float* __restrict__ w_dcn) {
    int idx = blockIdx.x * 256 + threadIdx.x;
    if (idx >= O_ * C_) return;
    int o = idx >> 8, c = idx & 255;
    int cb = c >> 6, k = c & 63;
    const float* src = w_dcn + ((size_t)o * C_ + c) * KK_;
#pragma unroll
    for (int kk = 0; kk < KK_; kk++) {
        g_Bhi[(size_t)(kk * 4 + cb) * (CK * O_) + k * O_ + o] = __float2half_rn(src[kk]);
    }
}

// ---------------------------------------------------------------------------
// Kernel 1b: w_off -> g_WoffHi/Lo
// ---------------------------------------------------------------------------
__global__ void prep_woff_kernel(const float* __restrict__ w_off) {
    int idx = blockIdx.x * 256 + threadIdx.x;
    if (idx >= NCH * CK * 32) return;
    int q  = idx >> 11;
    int r  = idx & 2047;
    int k  = r >> 5;
    int oc = r & 31;
    int kk = q >> 2, cb = q & 3;
    int c  = cb * 64 + k;
    float v = (oc < 18) ? w_off[((size_t)oc * C_ + c) * KK_ + kk] : 0.f;
    __half hi = __float2half_rn(v);
    __half lo = __float2half_rn(v - __half2float(hi));
    g_WoffHi[idx] = hi;
    g_WoffLo[idx] = lo;
}

// ---------------------------------------------------------------------------
// Kernel 2: offset conv via mma.sync, 2-term (AhBh + AhBl), A direct fp16.
// (R10 version: measured 65.7us)
// ---------------------------------------------------------------------------
#define OA_STR 72
#define OB_STR 40
#define OSM_BHI 18432
#define OSM_BLO 23552

__global__ __launch_bounds__(256, 2) void offset_mma_kernel(
    const float* __restrict__ x, const float* __restrict__ b_off) {
    __shared__ __align__(16) char sm[28672];
    __half (*AsHi)[OA_STR] = (__half(*)[OA_STR])(sm);
    __half (*BsHi)[OB_STR] = (__half(*)[OB_STR])(sm + OSM_BHI);
    __half (*BsLo)[OB_STR] = (__half(*)[OB_STR])(sm + OSM_BLO);

    int tid = threadIdx.x, lane = tid & 31, wid = tid >> 5;
    int blk = blockIdx.x;
    int b = blk >> 5, h0 = (blk & 31) * 2;
    int m0 = wid * 16;

    int m  = tid & 127;
    int cg = tid >> 7;                 // 0..1: 32 channels each
    int hh = h0 + (m >> 6);
    int wp = m & 63;
    const float* xb = x + (size_t)b * C_ * HW_;

    uint32_t aHi = smem_u32(sm) +
        (uint32_t)(((m0 + (lane & 15)) * OA_STR + ((lane >> 4) * 8)) * 2);
    uint32_t bHi = smem_u32(sm) + OSM_BHI +
        (uint32_t)(((((lane & 7) + 8 * ((lane >> 3) & 1)) * OB_STR) + 8 * (lane >> 4)) * 2);

    float d[3][4];
#pragma unroll
    for (int i = 0; i < 3; i++)
#pragma unroll
        for (int j = 0; j < 4; j++) d[i][j] = 0.f;

#pragma unroll 1
    for (int kk = 0; kk < KK_; kk++) {
        int ky = kk / 3, kx = kk % 3;
        int hy = hh - 1 + ky;
        int wx = wp - 1 + kx;
        bool vr = (hy >= 0 && hy < H_ && wx >= 0 && wx < W_);
        const float* xrow = xb + hy * W_ + wx;    // + c*HW_

#pragma unroll 1
        for (int cb = 0; cb < 4; cb++) {
            int q  = kk * 4 + cb;
            int c0 = cb * 64;

            // B fill
            {
                const float4* sH = (const float4*)(g_WoffHi + (size_t)q * (CK * 32));
                const float4* sL = (const float4*)(g_WoffLo + (size_t)q * (CK * 32));
                int row = tid >> 2, c4 = tid & 3;
                *(float4*)(&BsHi[row][c4 * 8]) = sH[tid];
                *(float4*)(&BsLo[row][c4 * 8]) = sL[tid];
            }

            // A fill: 32 channels/thread, fp16 direct
#pragma unroll
            for (int p = 0; p < 4; p++) {
                int cl = cg * 32 + 8 * p;
                __half2 hi[4];
#pragma unroll
                for (int u = 0; u < 4; u++) {
                    int c = c0 + cl + 2 * u;
                    float v0 = vr ? __ldg(xrow + (size_t)c * HW_) : 0.f;
                    float v1 = vr ? __ldg(xrow + (size_t)(c + 1) * HW_) : 0.f;
                    hi[u] = __floats2half2_rn(v0, v1);
                }
                *(float4*)(&AsHi[m][cl]) = *(float4*)hi;
            }
            __syncthreads();

#pragma unroll
            for (int ks = 0; ks < 4; ks++) {
                uint32_t a[4], bh[2][4], bl[2][4];
                uint32_t aOff = (uint32_t)(ks * 32);
                uint32_t bOff = (uint32_t)(ks * 16 * OB_STR * 2);
#pragma unroll
                for (int nq = 0; nq < 2; nq++) {
                    LDSM_X4T(bh[nq], bHi + bOff + nq * 32);
                    LDSM_X4T(bl[nq], bHi + (OSM_BLO - OSM_BHI) + bOff + nq * 32);
                }
                LDSM_X4(a, aHi + aOff);
#pragma unroll
                for (int nt = 0; nt < 3; nt++)
                    MMA16816(d[nt], a, bh[nt >> 1][(nt & 1) * 2], bh[nt >> 1][(nt & 1) * 2 + 1]);
#pragma unroll
                for (int nt = 0; nt < 3; nt++)
                    MMA16816(d[nt], a, bl[nt >> 1][(nt & 1) * 2], bl[nt >> 1][(nt & 1) * 2 + 1]);
            }
            __syncthreads();
        }
    }

#pragma unroll
    for (int nt = 0; nt < 3; nt++)
#pragma unroll
        for (int r = 0; r < 4; r++) {
            int mm = m0 + (lane >> 2) + ((r >= 2) ? 8 : 0);
            int oc = nt * 8 + (lane & 3) * 2 + (r & 1);
            if (oc < 18) {
                g_offset[((b * 18 + oc) * H_ + h0 + (mm >> 6)) * W_ + (mm & 63)]
                    = d[nt][r] + __ldg(b_off + oc);
            }
        }
}

// ---------------------------------------------------------------------------
// Kernel 3: fused bilinear sample + mma.sync single-term fp16 GEMM
// (R9 version: best measured dcn component, pair gathers)
// CTA = one (b,h): M=64, N=256. Ping-pong A, cp.async double-buffered B.
// ---------------------------------------------------------------------------
#define A_STR 72
#define B_STR 264
#define A_BUF 9216
#define SM_B   18432
#define B_BUF  33792
#define SM_TOT 86016

__device__ __forceinline__ void prefetch_b(uint32_t bs_base, int q, int tid) {
    const float4* src = (const float4*)(g_Bhi + (size_t)q * (CK * O_));
#pragma unroll
    for (int i = 0; i < 8; i++) {
        int e = tid + 256 * i;
        int row = e >> 5, c4 = e & 31;
        uint32_t dst = bs_base + (uint32_t)(row * B_STR + c4 * 8) * 2;
        CP_ASYNC16(dst, src + e);
    }
}

__global__ __launch_bounds__(256, 2) void dcn_mma_kernel(float* __restrict__ out) {
    extern __shared__ __align__(16) char sm[];
    uint32_t smb = smem_u32(sm);

    int tid = threadIdx.x, lane = tid & 31, wid = tid >> 5;
    int wm = wid >> 2, wn = wid & 3;
    int m0 = wm * 32, n0 = wn * 64;

    int blk = blockIdx.x;
    int b = blk >> 6, h = blk & 63;
    const __half2* xph_b = g_xph + (size_t)b * C_ * HW_;

    int m  = tid & 63;          // w position
    int cg = tid >> 6;          // 0..3: 16 channels each

    uint32_t aHi = smb +
        (uint32_t)(((m0 + (lane & 15)) * A_STR + ((lane >> 4) * 8)) * 2);
    uint32_t bBase = smb + SM_B +
        (uint32_t)(((((lane & 7) + 8 * ((lane >> 3) & 1)) * B_STR) + n0 + 8 * (lane >> 4)) * 2);

    float d[2][8][4];
#pragma unroll
    for (int i = 0; i < 2; i++)
#pragma unroll
        for (int j = 0; j < 8; j++)
#pragma unroll
            for (int k = 0; k < 4; k++) d[i][j][k] = 0.f;

    // prologue: prefetch B chunk 0 into buffer 0
    prefetch_b(smb + SM_B, 0, tid);
    CP_COMMIT();

    int buf = 0;
    int q = 0;

#pragma unroll 1
    for (int kk = 0; kk < KK_; kk++) {
        int ky = kk / 3, kx = kk % 3;
        float offy = g_offset[((b * 18 + kk * 2 + 0) * H_ + h) * W_ + m];
        float offx = g_offset[((b * 18 + kk * 2 + 1) * H_ + h) * W_ + m];
        float sy = offy + (float)(h - 1 + ky);
        float sx = offx + (float)(m - 1 + kx);
        float fy0 = floorf(sy), fx0 = floorf(sx);
        float fy = sy - fy0, fx = sx - fx0;
        int iy = (int)fy0, ix = (int)fx0;

        // x-pair weights (validity folded in; pad slot at w=W-1 holds 0)
        float wa, wb; int px;
        if (ix >= 0 && ix < W_ - 1)      { wa = 1.f - fx; wb = fx;  px = ix; }
        else if (ix == -1)               { wa = fx;       wb = 0.f; px = 0; }
        else if (ix == W_ - 1)           { wa = 1.f - fx; wb = 0.f; px = W_ - 1; }
        else                             { wa = 0.f;      wb = 0.f; px = 0; }
        // y-row weights
        float wy0 = (iy >= 0 && iy < H_) ? (1.f - fy) : 0.f;
        float wy1 = (iy + 1 >= 0 && iy + 1 < H_) ? fy : 0.f;
        int py0 = min(max(iy, 0), H_ - 1);
        int py1 = min(max(iy + 1, 0), H_ - 1);
        float w00 = wa * wy0, w01 = wb * wy0;
        float w10 = wa * wy1, w11 = wb * wy1;

        const __half2* p0base = xph_b + py0 * W_ + px;   // + c*HW_
        const __half2* p1base = xph_b + py1 * W_ + px;

#pragma unroll 1
        for (int cb = 0; cb < 4; cb++) {
            int c0 = cb * 64;

            // ---- A fill into ping-pong buffer (pair gathers) ----
            {
                char* aDst = sm + buf * A_BUF + (m * A_STR) * 2;
#pragma unroll
                for (int p = 0; p < 2; p++) {
                    int cl = cg * 16 + 8 * p;
                    __half2 hi[4];
#pragma unroll
                    for (int u = 0; u < 4; u++) {
                        int c = c0 + cl + 2 * u;
                        __half2 a0 = __ldg(p0base + (size_t)c * HW_);
                        __half2 a1 = __ldg(p1base + (size_t)c * HW_);
                        __half2 c0p = __ldg(p0base + (size_t)(c + 1) * HW_);
                        __half2 c1p = __ldg(p1base + (size_t)(c + 1) * HW_);
                        float2 fa0 = __half22float2(a0), fa1 = __half22float2(a1);
                        float2 fb0 = __half22float2(c0p), fb1 = __half22float2(c1p);
                        float v0 = w00 * fa0.x + w01 * fa0.y + w10 * fa1.x + w11 * fa1.y;
                        float v1 = w00 * fb0.x + w01 * fb0.y + w10 * fb1.x + w11 * fb1.y;
                        hi[u] = __floats2half2_rn(v0, v1);
                    }
                    *(float4*)(aDst + cl * 2) = *(float4*)hi;
                }
            }

            // B(q) must have arrived; all warps done with buf's prior contents
            CP_WAIT0();
            __syncthreads();

            // prefetch B(q+1) into the other buffer (safe: post-sync)
            if (q < NCH - 1) {
                prefetch_b(smb + SM_B + (buf ^ 1) * B_BUF, q + 1, tid);
                CP_COMMIT();
            }

            // ---- MMA on chunk q (single term) ----
            uint32_t aAddr = aHi + buf * A_BUF;
            uint32_t bAddr = bBase + buf * B_BUF;
#pragma unroll
            for (int ks = 0; ks < 4; ks++) {
                uint32_t a[2][4], bf[4][4];
                uint32_t aOff = (uint32_t)(ks * 32);
                uint32_t bOff = (uint32_t)(ks * 16 * B_STR * 2);
#pragma unroll
                for (int nq = 0; nq < 4; nq++) LDSM_X4T(bf[nq], bAddr + bOff + nq * 32);
#pragma unroll
                for (int mt = 0; mt < 2; mt++) LDSM_X4(a[mt], aAddr + aOff + mt * (16 * A_STR * 2));
#pragma unroll
                for (int mt = 0; mt < 2; mt++)
#pragma unroll
                    for (int nt = 0; nt < 8; nt++)
                        MMA16816(d[mt][nt], a[mt], bf[nt >> 1][(nt & 1) * 2], bf[nt >> 1][(nt & 1) * 2 + 1]);
            }

            buf ^= 1;
            q++;
        }
    }

    __syncthreads();

    // epilogue: smem transpose -> coalesced stores
    float (*bufp)[66] = (float(*)[66])(sm);
#pragma unroll 1
    for (int pass = 0; pass < 2; pass++) {
        if ((wn >> 1) == pass) {
            int nb = n0 - pass * 128;
#pragma unroll
            for (int mt = 0; mt < 2; mt++)
#pragma unroll
                for (int nt = 0; nt < 8; nt++) {
                    int rrow = m0 + mt * 16 + (lane >> 2);
                    int ccol = nb + nt * 8 + 2 * (lane & 3);
                    bufp[ccol][rrow]         = d[mt][nt][0];
                    bufp[ccol + 1][rrow]     = d[mt][nt][1];
                    bufp[ccol][rrow + 8]     = d[mt][nt][2];
                    bufp[ccol + 1][rrow + 8] = d[mt][nt][3];
                }
        }
        __syncthreads();
        float* obase = out + ((size_t)b * O_ + pass * 128) * HW_ + h * 64;
#pragma unroll
        for (int i = 0; i < 16; i++) {
            int e = tid + 256 * i;
            int nl = e >> 5, c2 = e & 31;
            float2 v = *(float2*)(&bufp[nl][c2 * 2]);
            *(float2*)(obase + (size_t)nl * HW_ + c2 * 2) = v;
        }
        __syncthreads();
    }
}

// ---------------------------------------------------------------------------
// Launch: fork-join graph.
//   default: prep_woff -> offset_mma ----\
//   s1:      prep_xpair -----------------+--> dcn_mma
//   s2:      prep_b ---------------------/
// Streams/events created once on the (uncaptured) correctness call.
// ---------------------------------------------------------------------------
extern "C" void kernel_launch(void* const* d_in, const int* in_sizes, int n_in,
                              void* d_out, int out_size) {
    const float* x     = (const float*)d_in[0];
    const float* w_off = (const float*)d_in[1];
    const float* b_off = (const float*)d_in[2];
    const float* w_dcn = (const float*)d_in[3];
    float* out = (float*)d_out;

    static cudaStream_t s1 = nullptr, s2 = nullptr;
    static cudaEvent_t e0 = nullptr, e1 = nullptr, e2 = nullptr;
    if (s1 == nullptr) {
        cudaStreamCreateWithFlags(&s1, cudaStreamNonBlocking);
        cudaStreamCreateWithFlags(&s2, cudaStreamNonBlocking);
        cudaEventCreateWithFlags(&e0, cudaEventDisableTiming);
        cudaEventCreateWithFlags(&e1, cudaEventDisableTiming);
        cudaEventCreateWithFlags(&e2, cudaEventDisableTiming);
        cudaFuncSetAttribute(dcn_mma_kernel,
                             cudaFuncAttributeMaxDynamicSharedMemorySize, SM_TOT);
    }

    // fork
    cudaEventRecord(e0, 0);
    cudaStreamWaitEvent(s1, e0, 0);
    cudaStreamWaitEvent(s2, e0, 0);

    // side branches
    prep_xpair_kernel<<<(B_ * C_ * HW_ + 255) / 256, 256, 0, s1>>>(x);
    prep_b_kernel<<<(O_ * C_ + 255) / 256, 256, 0, s2>>>(w_dcn);

    // main branch
    prep_woff_kernel<<<(NCH * CK * 32 + 255) / 256, 256>>>(w_off);
    offset_mma_kernel<<<B_ * H_ / 2, 256>>>(x, b_off);

    // join
    cudaEventRecord(e1, s1);
    cudaEventRecord(e2, s2);
    cudaStreamWaitEvent(0, e1, 0);
    cudaStreamWaitEvent(0, e2, 0);

    dcn_mma_kernel<<<B_ * H_, 256, SM_TOT>>>(out);
}